// round 8
// baseline (speedup 1.0000x reference)
#include <cuda_runtime.h>
#include <cuda_bf16.h>
#include <math.h>
#include <stdint.h>

#define B_ 8
#define N_ 4096
#define C_ 256
#define K_ 32
#define M_ (B_*N_)
#define TAU 3e-5f

// Scratch
__device__ __align__(16) float g_feat[M_*C_];
__device__ __align__(16) float g_pos[M_*C_];
__device__ __align__(16) __nv_bfloat16 g_p1[M_*C_];
__device__ __align__(16) __nv_bfloat16 g_p2[M_*C_];

__device__ __forceinline__ uint32_t smem_u32(const void* p) {
    uint32_t a;
    asm("{ .reg .u64 t; cvta.to.shared.u64 t, %1; cvt.u32.u64 %0, t; }"
        : "=r"(a) : "l"(p));
    return a;
}

#define CP_ASYNC16(dst, src) \
    asm volatile("cp.async.cg.shared.global [%0], [%1], 16;" :: "r"(dst), "l"(src))
#define CP_COMMIT() asm volatile("cp.async.commit_group;" ::: "memory")
#define CP_WAIT1()  asm volatile("cp.async.wait_group 1;" ::: "memory")
#define CP_WAIT0()  asm volatile("cp.async.wait_group 0;" ::: "memory")

#define MMA16816(d, av, b0, b1) \
    asm volatile("mma.sync.aligned.m16n8k16.row.col.f32.bf16.bf16.f32 " \
        "{%0,%1,%2,%3}, {%4,%5,%6,%7}, {%8,%9}, {%0,%1,%2,%3};" \
        : "+f"((d)[0]), "+f"((d)[1]), "+f"((d)[2]), "+f"((d)[3]) \
        : "r"((av).x), "r"((av).y), "r"((av).z), "r"((av).w), \
          "r"(b0), "r"(b1))

// ---------------------------------------------------------------------------
// Kernel 1: feat_pos = x @ W^T + bias ; split into g_feat / g_pos
// ---------------------------------------------------------------------------
__global__ __launch_bounds__(256) void gemm_feat_pos(
    const float* __restrict__ x, const float* __restrict__ W,
    const float* __restrict__ bias)
{
    __shared__ float as[16][64];
    __shared__ float bs[16][64];
    const int tid = threadIdx.x;
    const int row0 = blockIdx.y * 64;
    const int d0   = blockIdx.x * 64;
    const int tx = tid & 15, ty = tid >> 4;
    const int lr = tid >> 2, lc = tid & 3;
    float acc[4][4] = {};
    for (int kt = 0; kt < C_; kt += 16) {
        float4 va = *(const float4*)&x[(row0 + lr) * C_ + kt + lc * 4];
        float4 vb = *(const float4*)&W[(d0 + lr) * C_ + kt + lc * 4];
        as[lc*4+0][lr]=va.x; as[lc*4+1][lr]=va.y; as[lc*4+2][lr]=va.z; as[lc*4+3][lr]=va.w;
        bs[lc*4+0][lr]=vb.x; bs[lc*4+1][lr]=vb.y; bs[lc*4+2][lr]=vb.z; bs[lc*4+3][lr]=vb.w;
        __syncthreads();
        #pragma unroll
        for (int kk = 0; kk < 16; kk++) {
            float4 a = *(const float4*)&as[kk][ty*4];
            float4 b = *(const float4*)&bs[kk][tx*4];
            float ar[4]={a.x,a.y,a.z,a.w}, br[4]={b.x,b.y,b.z,b.w};
            #pragma unroll
            for (int i=0;i<4;i++)
                #pragma unroll
                for (int j=0;j<4;j++) acc[i][j] += ar[i]*br[j];
        }
        __syncthreads();
    }
    #pragma unroll
    for (int i=0;i<4;i++) {
        int row = row0 + ty*4 + i;
        #pragma unroll
        for (int j=0;j<4;j++) {
            int d = d0 + tx*4 + j;
            float v = acc[i][j] + bias[d];
            if (d < C_) g_feat[row*C_ + d] = v;
            else        g_pos[row*C_ + d - C_] = v;
        }
    }
}

// ---------------------------------------------------------------------------
// Kernel 2: normalize pos rows (write back fp32) + emit 2-term bf16 split.
// ---------------------------------------------------------------------------
__global__ __launch_bounds__(64) void norm_split()
{
    const int row = blockIdx.x;
    float* p = g_pos + (size_t)row * C_;
    const int t = threadIdx.x;
    float4 v = *(const float4*)&p[t*4];
    float ss = v.x*v.x + v.y*v.y + v.z*v.z + v.w*v.w;
    #pragma unroll
    for (int o = 16; o; o >>= 1) ss += __shfl_xor_sync(0xFFFFFFFFu, ss, o);
    __shared__ float s2[2];
    if ((t & 31) == 0) s2[t >> 5] = ss;
    __syncthreads();
    float inv = 1.0f / fmaxf(sqrtf(s2[0] + s2[1]), 1e-12f);
    float a[4] = {v.x*inv, v.y*inv, v.z*inv, v.w*inv};
    *(float4*)&p[t*4] = make_float4(a[0], a[1], a[2], a[3]);   // rescue path needs this
    __nv_bfloat16 b1[4], b2[4];
    #pragma unroll
    for (int e = 0; e < 4; e++) {
        b1[e] = __float2bfloat16(a[e]);
        float r = a[e] - __bfloat162float(b1[e]);
        b2[e] = __float2bfloat16(r);
    }
    size_t off = (size_t)row * C_ + t*4;
    *(__nv_bfloat162*)&g_p1[off]   = __nv_bfloat162(b1[0], b1[1]);
    *(__nv_bfloat162*)&g_p1[off+2] = __nv_bfloat162(b1[2], b1[3]);
    *(__nv_bfloat162*)&g_p2[off]   = __nv_bfloat162(b2[0], b2[1]);
    *(__nv_bfloat162*)&g_p2[off+2] = __nv_bfloat162(b2[2], b2[3]);
}

// ---------------------------------------------------------------------------
// Kernel 3: mma.sync bf16 (2-term split, 3 products) sim GEMM + top-32
//           + margin tracking + fp32 rescue of near-boundary rows
//           + softmax + gather.
// smem layout (bytes):
//   AFRAG [8 warps][2 terms][16 kc][32 lanes][16B]   0      .. 131072
//   BST   [2 stages][2 terms][64 keys][144B]         131072 .. 167936
//   S     float[128][65] (also rescue sims 4096f)    167936 .. 201216
//   TV    float[32][128]                             201216 .. 217600
//   TI    u16  [32][128]                             217600 .. 225792
// ---------------------------------------------------------------------------
#define AFRAG 0
#define BST   131072
#define SOFF  167936
#define TVOFF 201216
#define TIOFF 217600
#define SMEM_BYTES 225792
#define BSTAGE 18432
#define BTERM  9216

__device__ __forceinline__ void stage_fill(uint32_t smb, int buf, int g,
                                           size_t brow, int tid)
{
    const int tile = g >> 2, c = g & 3;
    const size_t kb = brow + tile * 64;
    #pragma unroll
    for (int i = 0; i < 4; i++) {
        int u = tid + i * 256;
        int term = u >> 9, rem = u & 511, key = rem >> 3, seg = rem & 7;
        const __nv_bfloat16* gp = term ? g_p2 : g_p1;
        const __nv_bfloat16* src = gp + ((kb + key) << 8) + c*64 + seg*8;
        uint32_t dst = smb + BST + buf*BSTAGE + term*BTERM + key*144 + seg*16;
        CP_ASYNC16(dst, src);
    }
}

__global__ __launch_bounds__(256, 1) void topk_attn(float* __restrict__ out)
{
    extern __shared__ char sm[];
    const uint32_t smb = smem_u32(sm);
    float* S  = (float*)(sm + SOFF);
    float* tv = (float*)(sm + TVOFF);
    uint16_t* ti = (uint16_t*)(sm + TIOFF);
    __shared__ int flagged[64];
    __shared__ int nflag;

    const int tid = threadIdx.x;
    const int w = tid >> 5, lane = tid & 31;
    const int batch = blockIdx.y;
    const int q0 = blockIdx.x * 128;
    const size_t brow = (size_t)batch * N_;
    if (tid == 0) nflag = 0;

    // ---- build A fragments (thread-local slots; no barrier needed) ----
    {
        const int r0 = q0 + w*16 + (lane >> 2);
        const int k00 = (lane & 3) * 2;
        #pragma unroll
        for (int t = 0; t < 2; t++) {
            const __nv_bfloat16* base = (t ? g_p2 : g_p1) + ((brow + r0) << 8);
            uint4* dst = (uint4*)(sm + AFRAG + (w*2 + t)*8192) + lane;
            #pragma unroll
            for (int kc = 0; kc < 16; kc++) {
                int k0 = kc*16 + k00;
                uint32_t w0 = *(const uint32_t*)(base + k0);
                uint32_t w1 = *(const uint32_t*)(base + 8*C_ + k0);
                uint32_t w2 = *(const uint32_t*)(base + k0 + 8);
                uint32_t w3 = *(const uint32_t*)(base + 8*C_ + k0 + 8);
                dst[kc*32] = make_uint4(w0, w1, w2, w3);
            }
        }
    }

    int cnt = 0, thrp = 0;
    float thrv = 3.0e38f;
    float rej  = -3.0e38f;      // runner-up (best rejected/evicted)
    float acc[8][4];

    stage_fill(smb, 0, 0, brow, tid);
    CP_COMMIT();

    for (int g = 0; g < 256; g++) {
        const int tile = g >> 2, c = g & 3;
        if (g + 1 < 256) {
            stage_fill(smb, (g + 1) & 1, g + 1, brow, tid);
            CP_COMMIT();
            CP_WAIT1();
        } else {
            CP_WAIT0();
        }
        __syncthreads();

        if (c == 0) {
            #pragma unroll
            for (int n = 0; n < 8; n++)
                #pragma unroll
                for (int e = 0; e < 4; e++) acc[n][e] = 0.f;
        }

        const char* bs = sm + BST + (g & 1) * BSTAGE;
        const char* bbase0 = bs + (lane >> 2)*144 + (lane & 3)*4;
        #pragma unroll
        for (int sub = 0; sub < 4; sub++) {
            const int kcg = c*4 + sub;
            uint4 a1 = *((const uint4*)(sm + AFRAG + (w*2 + 0)*8192) + kcg*32 + lane);
            uint4 a2 = *((const uint4*)(sm + AFRAG + (w*2 + 1)*8192) + kcg*32 + lane);
            const char* bbase = bbase0 + sub*32;
            #pragma unroll
            for (int n = 0; n < 8; n++) {
                const char* bp = bbase + n*1152;
                uint32_t b1lo = *(const uint32_t*)(bp);
                uint32_t b1hi = *(const uint32_t*)(bp + 16);
                uint32_t b2lo = *(const uint32_t*)(bp + BTERM);
                uint32_t b2hi = *(const uint32_t*)(bp + BTERM + 16);
                MMA16816(acc[n], a1, b1lo, b1hi);
                MMA16816(acc[n], a1, b2lo, b2hi);
                MMA16816(acc[n], a2, b1lo, b1hi);
            }
        }
        __syncthreads();

        if (c == 3) {
            const int r0 = w*16 + (lane >> 2);
            #pragma unroll
            for (int n = 0; n < 8; n++) {
                int col = n*8 + (lane & 3)*2;
                S[r0*65 + col]         = acc[n][0];
                S[r0*65 + col + 1]     = acc[n][1];
                S[(r0+8)*65 + col]     = acc[n][2];
                S[(r0+8)*65 + col + 1] = acc[n][3];
            }
            __syncthreads();
            if (tid < 128) {
                const int row = tid;
                const int kt0 = tile * 64;
                #pragma unroll 8
                for (int j = 0; j < 64; j++) {
                    float v = S[row*65 + j];
                    if (cnt < K_) {
                        tv[cnt*128 + row] = v; ti[cnt*128 + row] = (uint16_t)(kt0 + j);
                        if (v < thrv) { thrv = v; thrp = cnt; }
                        cnt++;
                    } else if (v > thrv) {
                        rej = fmaxf(rej, thrv);    // evicted value
                        tv[thrp*128 + row] = v; ti[thrp*128 + row] = (uint16_t)(kt0 + j);
                        thrv = tv[row]; thrp = 0;
                        #pragma unroll
                        for (int i = 1; i < K_; i++) {
                            float t2 = tv[i*128 + row];
                            if (t2 < thrv) { thrv = t2; thrp = i; }
                        }
                    } else {
                        rej = fmaxf(rej, v);       // rejected value
                    }
                }
            }
            __syncthreads();
        }
    }

    // ---- flag near-boundary rows ----
    if (tid < 128 && (thrv - rej) < TAU) {
        int idx = atomicAdd(&nflag, 1);
        if (idx < 64) flagged[idx] = tid;
    }
    __syncthreads();

    // ---- fp32 rescue: whole block recomputes each flagged row exactly ----
    {
        int nf = nflag; if (nf > 64) nf = 64;
        for (int f = 0; f < nf; f++) {
            const int row = flagged[f];
            const float4* qr = (const float4*)(g_pos + ((brow + q0 + row) << 8));
            #pragma unroll 2
            for (int kk = 0; kk < 16; kk++) {
                const int key = tid + kk*256;
                const float4* kr = (const float4*)(g_pos + ((brow + key) << 8));
                float d = 0.f;
                #pragma unroll 16
                for (int cc = 0; cc < 64; cc++) {
                    float4 qv = qr[cc], kv = kr[cc];
                    d += qv.x*kv.x + qv.y*kv.y + qv.z*kv.z + qv.w*kv.w;
                }
                S[key] = d;
            }
            __syncthreads();
            if (tid == 0) {
                int c2 = 0, p2 = 0; float t2v = 3.0e38f;
                for (int j = 0; j < N_; j++) {
                    float v = S[j];
                    if (c2 < K_) {
                        tv[c2*128 + row] = v; ti[c2*128 + row] = (uint16_t)j;
                        if (v < t2v) { t2v = v; p2 = c2; }
                        c2++;
                    } else if (v > t2v) {
                        tv[p2*128 + row] = v; ti[p2*128 + row] = (uint16_t)j;
                        t2v = tv[row]; p2 = 0;
                        #pragma unroll
                        for (int i = 1; i < K_; i++) {
                            float t2 = tv[i*128 + row];
                            if (t2 < t2v) { t2v = t2; p2 = i; }
                        }
                    }
                }
            }
            __syncthreads();
        }
    }

    // softmax per row (order-invariant)
    if (tid < 128) {
        const int row = tid;
        float m = -3.0e38f;
        #pragma unroll
        for (int i = 0; i < K_; i++) m = fmaxf(m, tv[i*128 + row]);
        float ssum = 0.f;
        #pragma unroll
        for (int i = 0; i < K_; i++) {
            float e = expf(tv[i*128 + row] - m);
            tv[i*128 + row] = e; ssum += e;
        }
        float inv = 1.0f / ssum;
        #pragma unroll
        for (int i = 0; i < K_; i++) tv[i*128 + row] *= inv;
    }
    __syncthreads();

    // gather: 8 warps, one row each, 8 floats/lane
    const float* fb = g_feat + (brow << 8);
    for (int rr = w; rr < 128; rr += 8) {
        float a0[4] = {0.f,0.f,0.f,0.f}, a1r[4] = {0.f,0.f,0.f,0.f};
        #pragma unroll 4
        for (int i = 0; i < K_; i++) {
            float wt = tv[i*128 + rr];
            const float* f = fb + ((size_t)ti[i*128 + rr] << 8) + lane*8;
            float4 u  = *(const float4*)f;
            float4 u2 = *(const float4*)(f + 4);
            a0[0]+=wt*u.x;  a0[1]+=wt*u.y;  a0[2]+=wt*u.z;  a0[3]+=wt*u.w;
            a1r[0]+=wt*u2.x; a1r[1]+=wt*u2.y; a1r[2]+=wt*u2.z; a1r[3]+=wt*u2.w;
        }
        float* o = out + ((brow + q0 + rr) << 8) + lane*8;
        *(float4*)o       = make_float4(a0[0],a0[1],a0[2],a0[3]);
        *(float4*)(o + 4) = make_float4(a1r[0],a1r[1],a1r[2],a1r[3]);
    }
}

// ---------------------------------------------------------------------------
extern "C" void kernel_launch(void* const* d_in, const int* in_sizes, int n_in,
                              void* d_out, int out_size)
{
    const float* x    = (const float*)d_in[0];
    const float* W    = (const float*)d_in[1];
    const float* bias = (const float*)d_in[2];
    float* out = (float*)d_out;

    gemm_feat_pos<<<dim3(512/64, M_/64), 256>>>(x, W, bias);
    norm_split<<<M_, 64>>>();

    cudaFuncSetAttribute(topk_attn, cudaFuncAttributeMaxDynamicSharedMemorySize,
                         SMEM_BYTES);
    topk_attn<<<dim3(N_/128, B_), 256, SMEM_BYTES>>>(out);
}